// round 12
// baseline (speedup 1.0000x reference)
#include <cuda_runtime.h>
#include <math.h>

#define THREADS 256
#define ELEMS   16
#define NFAST   (THREADS * ELEMS)   // 4096
#define CAP     512                 // per-side candidate cap

// Order-preserving float->uint key: monotonic increasing with float value.
__device__ __forceinline__ unsigned f2key(float v) {
    unsigned u = __float_as_uint(v);
    return u ^ (unsigned)(((int)u >> 31) | 0x80000000u);
}
__device__ __forceinline__ float key2f(unsigned key) {
    unsigned u = (key & 0x80000000u) ? (key ^ 0x80000000u) : ~key;
    return __uint_as_float(u);
}

// ========================= FAST kernel (n == 4096) ==========================
__global__ void __launch_bounds__(THREADS, 6)
wildcat_fast(const float* __restrict__ x, float* __restrict__ out,
             int kmax, int kmin, float alpha)
{
    __shared__ float     s_val[2 * CAP];     // top from 0, bottom from end
    __shared__ unsigned  s_c[8];
    __shared__ unsigned  s_c2[2];
    __shared__ long long s_loT, s_hiT, s_loB, s_hiB;
    __shared__ int       s_cAloT, s_cAhiT, s_cBloB, s_cBhiB;
    __shared__ int       s_refine, s_cntH, s_cntL;
    __shared__ unsigned  s_selH, s_selL;
    __shared__ int       s_resH, s_resL;
    __shared__ float     s_redf[2][THREADS / 32];

    const int tid  = threadIdx.x;
    const int lane = tid & 31;
    const int wid  = tid >> 5;
    const float* __restrict__ xr = x + (long long)blockIdx.x * NFAST;

    // ---- load 16 elements into registers (the only full-row memory pass) ----
    float v[ELEMS];
    {
        const float4* __restrict__ xr4 = (const float4*)xr;
        #pragma unroll
        for (int k = 0; k < 4; k++) {
            float4 t = xr4[tid + k * THREADS];
            v[4 * k + 0] = t.x; v[4 * k + 1] = t.y;
            v[4 * k + 2] = t.z; v[4 * k + 3] = t.w;
        }
    }
    if (tid < 8) s_c[tid] = 0;
    if (tid == 0) { s_cntH = 0; s_cntL = 0; }
    __syncthreads();

    // ---- sweep A: register-resident probe counts (pure ALU, no L1) ----
    {
        unsigned a0=0,a1=0,a2=0,a3=0,c0=0,c1=0,c2=0,c3=0;
        #pragma unroll
        for (int j = 0; j < ELEMS; j++) {
            float f = v[j];
            a0 += f >  0.72f; a1 += f >  0.80f; a2 += f >  0.88f; a3 += f >  0.96f;
            c0 += f < -0.96f; c1 += f < -0.88f; c2 += f < -0.80f; c3 += f < -0.72f;
        }
        a0 = __reduce_add_sync(0xFFFFFFFFu, a0);
        a1 = __reduce_add_sync(0xFFFFFFFFu, a1);
        a2 = __reduce_add_sync(0xFFFFFFFFu, a2);
        a3 = __reduce_add_sync(0xFFFFFFFFu, a3);
        c0 = __reduce_add_sync(0xFFFFFFFFu, c0);
        c1 = __reduce_add_sync(0xFFFFFFFFu, c1);
        c2 = __reduce_add_sync(0xFFFFFFFFu, c2);
        c3 = __reduce_add_sync(0xFFFFFFFFu, c3);
        if (lane == 0) {
            atomicAdd(&s_c[0], a0); atomicAdd(&s_c[1], a1);
            atomicAdd(&s_c[2], a2); atomicAdd(&s_c[3], a3);
            atomicAdd(&s_c[4], c0); atomicAdd(&s_c[5], c1);
            atomicAdd(&s_c[6], c2); atomicAdd(&s_c[7], c3);
        }
    }
    __syncthreads();

    // ---- bracket selection from probe counts ----
    if (tid == 0) {
        const float pT[4] = {0.72f, 0.80f, 0.88f, 0.96f};
        const float pB[4] = {-0.96f, -0.88f, -0.80f, -0.72f};
        unsigned km = (unsigned)kmax, kn = (unsigned)kmin;
        long long lo, hi; int cAlo, cAhi;
        if (s_c[0] < km)       { lo = -1;                      hi = (long long)f2key(pT[0]); cAlo = NFAST;       cAhi = (int)s_c[0]; }
        else if (s_c[3] >= km) { lo = (long long)f2key(pT[3]); hi = 0xFFFFFFFFLL;            cAlo = (int)s_c[3]; cAhi = 0; }
        else {
            int j = (s_c[2] >= km) ? 2 : (s_c[1] >= km) ? 1 : 0;
            lo = (long long)f2key(pT[j]); hi = (long long)f2key(pT[j + 1]);
            cAlo = (int)s_c[j]; cAhi = (int)s_c[j + 1];
        }
        s_loT = lo; s_hiT = hi; s_cAloT = cAlo; s_cAhiT = cAhi;

        long long lob, hib; int cBlo, cBhi;
        if (s_c[7] < kn)       { lob = (long long)f2key(pB[3]); hib = 0x100000000LL;           cBlo = (int)s_c[7]; cBhi = NFAST; }
        else if (s_c[4] >= kn) { lob = 0;                       hib = (long long)f2key(pB[0]); cBlo = 0;           cBhi = (int)s_c[4]; }
        else {
            int j = (s_c[5] >= kn) ? 0 : (s_c[6] >= kn) ? 1 : 2;
            lob = (long long)f2key(pB[j]); hib = (long long)f2key(pB[j + 1]);
            cBlo = (int)s_c[4 + j]; cBhi = (int)s_c[4 + j + 1];
        }
        s_loB = lob; s_hiB = hib; s_cBloB = cBlo; s_cBhiB = cBhi;

        bool needT = (cAlo - cAhi > CAP) && (hi - lo > 1);
        bool needB = (cBhi - cBlo > CAP) && (hib - lob > 1);
        s_refine = (needT || needB) ? 1 : 0;
    }
    __syncthreads();

    // ---- exact binary-search refinement (rare; key-space, register counts) --
    while (true) {
        if (!s_refine) break;
        if (tid < 2) s_c2[tid] = 0;
        const long long midT = (s_loT + s_hiT) >> 1;
        const long long midB = (s_loB + s_hiB) >> 1;
        __syncthreads();
        unsigned ct = 0, cb = 0;
        #pragma unroll
        for (int j = 0; j < ELEMS; j++) {
            long long k = (long long)f2key(v[j]);
            ct += (k > midT);
            cb += (k < midB);
        }
        ct = __reduce_add_sync(0xFFFFFFFFu, ct);
        cb = __reduce_add_sync(0xFFFFFFFFu, cb);
        if (lane == 0) { atomicAdd(&s_c2[0], ct); atomicAdd(&s_c2[1], cb); }
        __syncthreads();
        if (tid == 0) {
            bool needT = (s_cAloT - s_cAhiT > CAP) && (s_hiT - s_loT > 1);
            if (needT) {
                int c = (int)s_c2[0];
                if (c >= kmax) { s_loT = midT; s_cAloT = c; }
                else           { s_hiT = midT; s_cAhiT = c; }
            }
            bool needB = (s_cBhiB - s_cBloB > CAP) && (s_hiB - s_loB > 1);
            if (needB) {
                int c = (int)s_c2[1];
                if (c >= kmin) { s_hiB = midB; s_cBhiB = c; }
                else           { s_loB = midB; s_cBloB = c; }
            }
            needT = (s_cAloT - s_cAhiT > CAP) && (s_hiT - s_loT > 1);
            needB = (s_cBhiB - s_cBloB > CAP) && (s_hiB - s_loB > 1);
            s_refine = (needT || needB) ? 1 : 0;
        }
        __syncthreads();
    }

    const long long hiT64 = s_hiT, loB64 = s_loB;
    const bool skipT = (s_hiT - s_loT) == 1;    // bracket is a single key value
    const bool skipB = (s_hiB - s_loB) == 1;
    const int  krH = kmax - s_cAhiT;            // rank within top bracket (>=1)
    const int  krL = kmin - s_cBloB;            // rank within bottom bracket (>=1)
    // 32-bit clamped bounds for the hot sweep:
    const unsigned uLoT = (unsigned)(s_loT + 1);                      // k >= uLoT  <=> k > loT
    const unsigned uHiT = (unsigned)((s_hiT > 0xFFFFFFFFLL) ? 0xFFFFFFFFLL : s_hiT); // k > uHiT <=> k > hiT
    const unsigned uLoB = (unsigned)s_loB;                            // k < uLoB  <=> k < loB
    const unsigned uHiB = (unsigned)(s_hiB - 1);                      // k <= uHiB <=> k < hiB

    // ---- sweep B: strict-side sums + candidate compaction (registers) -------
    float sumT = 0.0f, sumB = 0.0f;
    #pragma unroll
    for (int j = 0; j < ELEMS; j++) {
        float f = v[j];
        unsigned k = f2key(f);
        if (k > uHiT) sumT += f;
        else if (!skipT && k >= uLoT) { int p = atomicAdd(&s_cntH, 1); s_val[p] = f; }
        if (k < uLoB) sumB += f;
        else if (!skipB && k <= uHiB) { int p = atomicAdd(&s_cntL, 1); s_val[2 * CAP - 1 - p] = f; }
    }
    __syncthreads();

    const int cntH = s_cntH, cntL = s_cntL;

    // ---- quadratic rank-select over tiny candidate lists --------------------
    // For each candidate: cg = #keys strictly greater, ce = #keys equal.
    // Threshold candidate: cg < krH <= cg+ce. Also: key > keyH <=> cg+ce < krH.
    for (int c = tid; c < cntH; c += THREADS) {
        float fc = s_val[c];
        unsigned kc = f2key(fc);
        int cg = 0, ce = 0;
        for (int j = 0; j < cntH; j++) {
            unsigned kj = f2key(s_val[j]);
            cg += (kj > kc);
            ce += (kj == kc);
        }
        if (cg + ce < krH) sumT += fc;                       // strictly above threshold
        if (cg < krH && krH <= cg + ce) { s_selH = kc; s_resH = krH - cg; }
    }
    for (int c = tid; c < cntL; c += THREADS) {
        float fc = s_val[2 * CAP - 1 - c];
        unsigned kc = f2key(fc);
        int cl = 0, ce = 0;
        for (int j = 0; j < cntL; j++) {
            unsigned kj = f2key(s_val[2 * CAP - 1 - j]);
            cl += (kj < kc);
            ce += (kj == kc);
        }
        if (cl + ce < krL) sumB += fc;                       // strictly below threshold
        if (cl < krL && krL <= cl + ce) { s_selL = kc; s_resL = krL - cl; }
    }
    __syncthreads();

    const unsigned keyH = skipT ? (unsigned)hiT64 : s_selH;
    const unsigned keyL = skipB ? (unsigned)loB64 : s_selL;
    const int resH = skipT ? krH : s_resH;
    const int resL = skipB ? krL : s_resL;

    // ---- block reduction + epilogue -----------------------------------------
    #pragma unroll
    for (int o = 16; o > 0; o >>= 1) {
        sumT += __shfl_xor_sync(0xFFFFFFFFu, sumT, o);
        sumB += __shfl_xor_sync(0xFFFFFFFFu, sumB, o);
    }
    if (lane == 0) { s_redf[0][wid] = sumT; s_redf[1][wid] = sumB; }
    __syncthreads();

    if (tid == 0) {
        float st = 0.0f, sb = 0.0f;
        #pragma unroll
        for (int w = 0; w < THREADS / 32; ++w) { st += s_redf[0][w]; sb += s_redf[1][w]; }
        st += (float)resH * key2f(keyH);    // exact tie handling
        sb += (float)resL * key2f(keyL);
        out[blockIdx.x] = st / (float)kmax + (alpha / (float)kmin) * sb;
    }
}

// ================= GENERIC fallback (any n) — proven R8 path ================
template<int NB, bool DESC>
__device__ __forceinline__ void resolve_small(const unsigned* __restrict__ hist, int krem,
                                              int lane, unsigned &bin, int &krem_out)
{
    constexpr int BPL = NB / 32;
    unsigned s = 0;
    #pragma unroll
    for (int j = 0; j < BPL; j++) {
        int b = DESC ? (NB - 1 - (lane * BPL + j)) : (lane * BPL + j);
        s += hist[b];
    }
    unsigned p = s;
    #pragma unroll
    for (int o = 1; o < 32; o <<= 1) {
        unsigned t = __shfl_up_sync(0xFFFFFFFFu, p, o);
        if (lane >= o) p += t;
    }
    unsigned excl = p - s;
    bool cross = (excl < (unsigned)krem) && (p >= (unsigned)krem);
    unsigned m = __ballot_sync(0xFFFFFFFFu, cross);
    int src = __ffs(m) - 1;
    unsigned bsel = 0; int k2 = 0;
    if (cross) {
        unsigned cum = excl;
        #pragma unroll
        for (int j = 0; j < BPL; j++) {
            int b = DESC ? (NB - 1 - (lane * BPL + j)) : (lane * BPL + j);
            unsigned c = hist[b];
            if (cum + c >= (unsigned)krem) { bsel = (unsigned)b; k2 = krem - (int)cum; break; }
            cum += c;
        }
    }
    bin = __shfl_sync(0xFFFFFFFFu, bsel, src);
    krem_out = __shfl_sync(0xFFFFFFFFu, k2, src);
}

template<bool DESC>
__device__ __forceinline__ void resolve_big(const unsigned* __restrict__ hist, int krem,
                                            int lane, unsigned &bin, int &krem_out)
{
    const uint4* h4 = (const uint4*)hist;
    unsigned s = 0;
    #pragma unroll
    for (int j = 0; j < 32; j++) {
        uint4 c = h4[lane * 32 + j];
        s += c.x + c.y + c.z + c.w;
    }
    unsigned p = s;
    if (DESC) {
        #pragma unroll
        for (int o = 1; o < 32; o <<= 1) {
            unsigned t = __shfl_down_sync(0xFFFFFFFFu, p, o);
            if (lane + o < 32) p += t;
        }
    } else {
        #pragma unroll
        for (int o = 1; o < 32; o <<= 1) {
            unsigned t = __shfl_up_sync(0xFFFFFFFFu, p, o);
            if (lane >= o) p += t;
        }
    }
    unsigned excl = p - s;
    bool cross = (excl < (unsigned)krem) && (p >= (unsigned)krem);
    unsigned m = __ballot_sync(0xFFFFFFFFu, cross);
    int src = __ffs(m) - 1;
    unsigned bsel = 0; int k2 = 0;
    if (cross) {
        unsigned cum = excl;
        if (DESC) {
            for (int b = lane * 128 + 127; b >= lane * 128; --b) {
                unsigned c = hist[b];
                if (cum + c >= (unsigned)krem) { bsel = (unsigned)b; k2 = krem - (int)cum; break; }
                cum += c;
            }
        } else {
            for (int b = lane * 128; b < lane * 128 + 128; ++b) {
                unsigned c = hist[b];
                if (cum + c >= (unsigned)krem) { bsel = (unsigned)b; k2 = krem - (int)cum; break; }
                cum += c;
            }
        }
    }
    bin = __shfl_sync(0xFFFFFFFFu, bsel, src);
    krem_out = __shfl_sync(0xFFFFFFFFu, k2, src);
}

__global__ void __launch_bounds__(THREADS, 8)
wildcat_generic(const float* __restrict__ x, float* __restrict__ out,
                int n, int kmax, int kmin, float alpha)
{
    __shared__ unsigned s_mem[4096];
    __shared__ unsigned s_subh[512];
    __shared__ unsigned s_selH, s_selL;
    __shared__ int      s_kremH, s_kremL, s_cntH, s_cntL;
    __shared__ float    s_red[2][THREADS / 32];
    float* s_val = (float*)s_mem;

    const int tid  = threadIdx.x;
    const int lane = tid & 31;
    const int wid  = tid >> 5;
    const float* __restrict__ xr = x + (long long)blockIdx.x * n;

    for (int b = tid; b < 4096; b += THREADS) s_mem[b] = 0;
    if (tid == 0) { s_cntH = 0; s_cntL = 0; }
    __syncthreads();

    for (int i = tid; i < n; i += THREADS)
        atomicAdd(&s_mem[f2key(xr[i]) >> 20], 1u);
    __syncthreads();

    if (wid == 0) {
        unsigned b; int k2;
        resolve_big<true>(s_mem, kmax, lane, b, k2);
        if (lane == 0) { s_selH = b; s_kremH = k2; }
    } else if (wid == 1) {
        unsigned b; int k2;
        resolve_big<false>(s_mem, kmin, lane, b, k2);
        if (lane == 0) { s_selL = b; s_kremL = k2; }
    }
    __syncthreads();
    const unsigned binH = s_selH, binL = s_selL;
    const bool sameBin = (binH == binL);
    __syncthreads();

    float sumT = 0.0f, sumB = 0.0f;
    for (int i = tid; i < n; i += THREADS) {
        float f = xr[i];
        unsigned b = f2key(f) >> 20;
        if (b > binH) sumT += f;
        if (b < binL) sumB += f;
        if (b == binH) { int p = atomicAdd(&s_cntH, 1); s_val[p] = f; }
        else if (b == binL) { int p = atomicAdd(&s_cntL, 1); s_val[4095 - p] = f; }
    }
    __syncthreads();
    const int cntH = min(s_cntH, 4096);
    const int cntL = sameBin ? cntH : min(s_cntL, 4096);

    #pragma unroll 1
    for (int l = 0; l < 3; l++) {
        const int fs = (l == 0) ? 20 : (l == 1) ? 12 : 6;
        const int sh = (l == 0) ? 12 : (l == 1) ? 6 : 0;
        const unsigned mk = (l == 0) ? 0xFFu : 0x3Fu;
        const int nb = (l == 0) ? 256 : 64;
        const unsigned pH = s_selH, pL = s_selL;
        if (tid < nb) { s_subh[tid] = 0; s_subh[tid + 256] = 0; }
        __syncthreads();
        for (int t = tid; t < cntH; t += THREADS) {
            unsigned key = f2key(s_val[t]);
            if ((key >> fs) == pH) atomicAdd(&s_subh[(key >> sh) & mk], 1u);
        }
        for (int t = tid; t < cntL; t += THREADS) {
            float f = sameBin ? s_val[t] : s_val[4095 - t];
            unsigned key = f2key(f);
            if ((key >> fs) == pL) atomicAdd(&s_subh[256 + ((key >> sh) & mk)], 1u);
        }
        __syncthreads();
        if (wid == 0) {
            unsigned b; int k2;
            if (nb == 256) resolve_small<256, true>(s_subh, s_kremH, lane, b, k2);
            else           resolve_small<64,  true>(s_subh, s_kremH, lane, b, k2);
            if (lane == 0) { s_selH = (pH << ((l == 0) ? 8 : 6)) | b; s_kremH = k2; }
        } else if (wid == 1) {
            unsigned b; int k2;
            if (nb == 256) resolve_small<256, false>(s_subh + 256, s_kremL, lane, b, k2);
            else           resolve_small<64,  false>(s_subh + 256, s_kremL, lane, b, k2);
            if (lane == 0) { s_selL = (pL << ((l == 0) ? 8 : 6)) | b; s_kremL = k2; }
        }
        __syncthreads();
    }

    const unsigned keyH = s_selH, keyL = s_selL;
    for (int t = tid; t < cntH; t += THREADS) {
        float f = s_val[t];
        if (f2key(f) > keyH) sumT += f;
    }
    for (int t = tid; t < cntL; t += THREADS) {
        float f = sameBin ? s_val[t] : s_val[4095 - t];
        if (f2key(f) < keyL) sumB += f;
    }
    #pragma unroll
    for (int o = 16; o > 0; o >>= 1) {
        sumT += __shfl_xor_sync(0xFFFFFFFFu, sumT, o);
        sumB += __shfl_xor_sync(0xFFFFFFFFu, sumB, o);
    }
    if (lane == 0) { s_red[0][wid] = sumT; s_red[1][wid] = sumB; }
    __syncthreads();
    if (tid == 0) {
        float st = 0.0f, sb = 0.0f;
        #pragma unroll
        for (int w = 0; w < THREADS / 32; ++w) { st += s_red[0][w]; sb += s_red[1][w]; }
        st += (float)s_kremH * key2f(keyH);
        sb += (float)s_kremL * key2f(keyL);
        out[blockIdx.x] = st / (float)kmax + (alpha / (float)kmin) * sb;
    }
}

extern "C" void kernel_launch(void* const* d_in, const int* in_sizes, int n_in,
                              void* d_out, int out_size)
{
    const float* x = (const float*)d_in[0];
    float* out = (float*)d_out;

    const int rows = out_size;                 // 32*512 = 16384
    const int n = in_sizes[0] / rows;          // 4096
    int kmax = (int)lrintf(0.2f * (float)n);   // int(round(0.2*n)) = 819
    int kmin = (int)lrintf(0.2f * (float)n);
    if (kmax < 1) kmax = 1;
    if (kmin < 1) kmin = 1;

    if (n == NFAST)
        wildcat_fast<<<rows, THREADS>>>(x, out, kmax, kmin, 0.7f);
    else
        wildcat_generic<<<rows, THREADS>>>(x, out, n, kmax, kmin, 0.7f);
}